// round 13
// baseline (speedup 1.0000x reference)
#include <cuda_runtime.h>

// RNN: B=4096, T=512, I=1, H=16, O=1
//   h_t = tanh(x_t*w_ih + b_ih + b_hh + W_hh h_{t-1}), h_0=0
//   out[b] = dot(h_T, w_fc) + b_fc
//
// R13: rotated self-first gather. Mapping (R10/R12): 8 lanes/element,
// lane m owns rows {2m,2m+1} packed as f32x2 state hq; 4 elements/warp.
// Lane m fetches pair k from lane (m+k)&7 with weights PRE-ROTATED to
// match, so:
//   - k=0 is the lane's own pair (no shuffle): 16 -> 14 SHFL.32/step and
//     both trees' first fma2 issues right after the tanh/pack, in
//     parallel with the remaining shuffle issues;
//   - shuffles are issued in tree-consumption order, so only the last
//     pair's 26cy latency is exposed and late tree ops hide under it.
// Kept: f32 datapath (R11 fp16 failed the gate), packed f32x2 trees,
// tanh.approx.f32, x staged in smem.

#define RNN_B 4096
#define RNN_T 512
#define RNN_H 16
#define XROW (RNN_T + 4)   // x row pad: groups' reads on distinct banks

__device__ __forceinline__ float tanh_approx(float x) {
    float y; asm("tanh.approx.f32 %0, %1;" : "=f"(y) : "f"(x)); return y;
}
__device__ __forceinline__ unsigned long long mul2(unsigned long long a, unsigned long long b) {
    unsigned long long d; asm("mul.rn.f32x2 %0, %1, %2;" : "=l"(d) : "l"(a), "l"(b)); return d;
}
__device__ __forceinline__ unsigned long long fma2(unsigned long long a, unsigned long long b, unsigned long long c) {
    unsigned long long d; asm("fma.rn.f32x2 %0, %1, %2, %3;" : "=l"(d) : "l"(a), "l"(b), "l"(c)); return d;
}
__device__ __forceinline__ unsigned long long add2(unsigned long long a, unsigned long long b) {
    unsigned long long d; asm("add.rn.f32x2 %0, %1, %2;" : "=l"(d) : "l"(a), "l"(b)); return d;
}
__device__ __forceinline__ unsigned long long packf2(float lo, float hi) {
    unsigned long long d; asm("mov.b64 %0, {%1, %2};" : "=l"(d) : "f"(lo), "f"(hi)); return d;
}
__device__ __forceinline__ float2 unpackf2(unsigned long long p) {
    float lo, hi; asm("mov.b64 {%0, %1}, %2;" : "=f"(lo), "=f"(hi) : "l"(p));
    return make_float2(lo, hi);
}

__global__ __launch_bounds__(32) void rnn_scan_kernel(
    const float* __restrict__ x,      // [B, T, 1]
    const float* __restrict__ w_ih,   // [H]
    const float* __restrict__ w_hh,   // [H, H]
    const float* __restrict__ b_ih,   // [H]
    const float* __restrict__ b_hh,   // [H]
    const float* __restrict__ w_fc,   // [H]
    const float* __restrict__ b_fc,   // [1]
    float* __restrict__ out)          // [B]
{
    __shared__ __align__(16) float sx[4 * XROW];  // 4 sequences of x (~8.3KB)

    const int warp = blockIdx.x;      // one warp per block
    const int lane = threadIdx.x;     // 0..31
    const int g    = lane >> 3;       // element within warp (0..3)
    const int m    = lane & 7;        // lane within 8-lane group

    const int e  = warp * 4 + g;      // batch element, < 4096
    const int j0 = 2 * m;             // first owned row
    const int j1 = 2 * m + 1;         // second owned row

    // ---- Preload this warp's 4 contiguous x sequences (8KB) into smem. ----
    {
        const float4* src = reinterpret_cast<const float4*>(x + (long)warp * 4 * RNN_T);
        #pragma unroll
        for (int i = 0; i < 16; i++) {
            const int idx = i * 32 + lane;        // float4 index 0..511
            const float4 v = src[idx];
            const int f   = idx * 4;
            const int row = f >> 9;               // /512
            const int col = f & 511;
            *reinterpret_cast<float4*>(&sx[row * XROW + col]) = v;
        }
    }
    __syncwarp();

    // Rotated packed weights: pair slot k corresponds to source lane
    // q = (m+k)&7, i.e. h-columns {2q, 2q+1}.
    //   wr0[k] = (w[j0][2q], w[j0][2q+1]),  wr1[k] = same for row j1.
    unsigned long long wr0[8], wr1[8];
    {
        const float* wa = w_hh + j0 * RNN_H;
        const float* wb = w_hh + j1 * RNN_H;
        #pragma unroll
        for (int k = 0; k < 8; k++) {
            const int q = (m + k) & 7;
            wr0[k] = packf2(wa[2 * q], wa[2 * q + 1]);
            wr1[k] = packf2(wb[2 * q], wb[2 * q + 1]);
        }
    }
    const float wih0  = w_ih[j0];
    const float wih1  = w_ih[j1];
    const float bias0 = b_ih[j0] + b_hh[j0];
    const float bias1 = b_ih[j1] + b_hh[j1];

    // Per-lane rotated source indices (hoisted out of the loop).
    int src1 = (m + 1) & 7, src2 = (m + 2) & 7, src3 = (m + 3) & 7,
        src4 = (m + 4) & 7, src5 = (m + 5) & 7, src6 = (m + 6) & 7,
        src7 = (m + 7) & 7;

    const float4* sx4 = reinterpret_cast<const float4*>(&sx[g * XROW]);

    // Lane state: packed (h_j0, h_j1) f32x2 — also the shuffle payload.
    unsigned long long hq = packf2(0.0f, 0.0f);

    #pragma unroll 1
    for (int t4 = 0; t4 < RNN_T / 4; t4++) {
        const float4 xv = sx4[t4];    // broadcast LDS.128 within each group
        const float xs[4] = {xv.x, xv.y, xv.z, xv.w};
        #pragma unroll
        for (int s = 0; s < 4; s++) {
            // x-terms (off critical path), seeded into tree-accum 0 addends.
            const unsigned long long seed0 = packf2(fmaf(xs[s], wih0, bias0), 0.0f);
            const unsigned long long seed1 = packf2(fmaf(xs[s], wih1, bias1), 0.0f);

            // Own pair first: both trees start immediately (no shuffle).
            unsigned long long a0 = fma2(wr0[0], hq, seed0);
            unsigned long long b0 = fma2(wr1[0], hq, seed1);

            // Rotated gather of the other 7 pairs, issued in the order
            // the trees consume them.
            const unsigned long long p1 = __shfl_sync(0xffffffffu, hq, src1, 8);
            const unsigned long long p2 = __shfl_sync(0xffffffffu, hq, src2, 8);
            const unsigned long long p3 = __shfl_sync(0xffffffffu, hq, src3, 8);
            const unsigned long long p4 = __shfl_sync(0xffffffffu, hq, src4, 8);
            const unsigned long long p5 = __shfl_sync(0xffffffffu, hq, src5, 8);
            const unsigned long long p6 = __shfl_sync(0xffffffffu, hq, src6, 8);
            const unsigned long long p7 = __shfl_sync(0xffffffffu, hq, src7, 8);

            unsigned long long a1 = mul2(wr0[1], p1);
            unsigned long long b1 = mul2(wr1[1], p1);
            unsigned long long a2 = mul2(wr0[2], p2);
            unsigned long long b2 = mul2(wr1[2], p2);
            unsigned long long a3 = mul2(wr0[3], p3);
            unsigned long long b3 = mul2(wr1[3], p3);
            a0 = fma2(wr0[4], p4, a0);
            b0 = fma2(wr1[4], p4, b0);
            a1 = fma2(wr0[5], p5, a1);
            b1 = fma2(wr1[5], p5, b1);
            a2 = fma2(wr0[6], p6, a2);
            b2 = fma2(wr1[6], p6, b2);
            a3 = fma2(wr0[7], p7, a3);
            b3 = fma2(wr1[7], p7, b3);
            a0 = add2(a0, a1);
            b0 = add2(b0, b1);
            a2 = add2(a2, a3);
            b2 = add2(b2, b3);
            a0 = add2(a0, a2);
            b0 = add2(b0, b2);
            const float2 prA = unpackf2(a0);
            const float2 prB = unpackf2(b0);

            const float h0 = tanh_approx(prA.x + prA.y);
            const float h1 = tanh_approx(prB.x + prB.y);
            hq = packf2(h0, h1);      // single pack per step
        }
    }

    // out[e] = sum_j h[j]*w_fc[j] + b_fc  (reduce over the 8-lane group)
    const float2 hf = unpackf2(hq);
    float v = hf.x * w_fc[j0] + hf.y * w_fc[j1];
    #pragma unroll
    for (int off = 4; off; off >>= 1)
        v += __shfl_xor_sync(0xffffffffu, v, off, 8);
    if (m == 0)
        out[e] = v + b_fc[0];
}

extern "C" void kernel_launch(void* const* d_in, const int* in_sizes, int n_in,
                              void* d_out, int out_size) {
    const float* x    = (const float*)d_in[0];
    const float* w_ih = (const float*)d_in[1];
    const float* w_hh = (const float*)d_in[2];
    const float* b_ih = (const float*)d_in[3];
    const float* b_hh = (const float*)d_in[4];
    const float* w_fc = (const float*)d_in[5];
    const float* b_fc = (const float*)d_in[6];
    float* out = (float*)d_out;

    // 1024 single-warp blocks; 4 batch elements per warp, 8 lanes each.
    rnn_scan_kernel<<<RNN_B / 4, 32>>>(x, w_ih, w_hh, b_ih, b_hh, w_fc, b_fc, out);
}

// round 14
// speedup vs baseline: 1.1290x; 1.1290x over previous
#include <cuda_runtime.h>

// RNN: B=4096, T=512, I=1, H=16, O=1
//   h_t = tanh(x_t*w_ih + b_ih + b_hh + W_hh h_{t-1}), h_0=0
//   out[b] = dot(h_T, w_fc) + b_fc
//
// R14 = R12 + chain schedule surgery (R13's rotated gather regressed:
// register-source shuffles cost more than the 2 saved SHFLs — immediate
// lanes only).
//   - Late merge: pairs p0..p6 reduce to `partial` while p7 is in flight;
//     acc = fma2(w7, p7, partial). Tail after last arrival: fma2+FADD+tanh.
//   - Seeds for all 4 substeps hoisted to the xv load (off-chain).
//   - Shuffles emitted immediately after the hq pack, in consumption order.
// Mapping: 8 lanes/element, lane m owns rows {2m,2m+1} packed as f32x2 in
// hq (also the shuffle payload); 4 elements/warp; 1024 single-warp blocks;
// x staged in smem; tanh.approx.f32; packed f32x2 trees.

#define RNN_B 4096
#define RNN_T 512
#define RNN_H 16
#define XROW (RNN_T + 4)   // x row pad: groups' reads on distinct banks

__device__ __forceinline__ float tanh_approx(float x) {
    float y; asm("tanh.approx.f32 %0, %1;" : "=f"(y) : "f"(x)); return y;
}
__device__ __forceinline__ unsigned long long mul2(unsigned long long a, unsigned long long b) {
    unsigned long long d; asm("mul.rn.f32x2 %0, %1, %2;" : "=l"(d) : "l"(a), "l"(b)); return d;
}
__device__ __forceinline__ unsigned long long fma2(unsigned long long a, unsigned long long b, unsigned long long c) {
    unsigned long long d; asm("fma.rn.f32x2 %0, %1, %2, %3;" : "=l"(d) : "l"(a), "l"(b), "l"(c)); return d;
}
__device__ __forceinline__ unsigned long long add2(unsigned long long a, unsigned long long b) {
    unsigned long long d; asm("add.rn.f32x2 %0, %1, %2;" : "=l"(d) : "l"(a), "l"(b)); return d;
}
__device__ __forceinline__ unsigned long long packf2(float lo, float hi) {
    unsigned long long d; asm("mov.b64 %0, {%1, %2};" : "=l"(d) : "f"(lo), "f"(hi)); return d;
}
__device__ __forceinline__ float2 unpackf2(unsigned long long p) {
    float lo, hi; asm("mov.b64 {%0, %1}, %2;" : "=f"(lo), "=f"(hi) : "l"(p));
    return make_float2(lo, hi);
}

__global__ __launch_bounds__(32) void rnn_scan_kernel(
    const float* __restrict__ x,      // [B, T, 1]
    const float* __restrict__ w_ih,   // [H]
    const float* __restrict__ w_hh,   // [H, H]
    const float* __restrict__ b_ih,   // [H]
    const float* __restrict__ b_hh,   // [H]
    const float* __restrict__ w_fc,   // [H]
    const float* __restrict__ b_fc,   // [1]
    float* __restrict__ out)          // [B]
{
    __shared__ __align__(16) float sx[4 * XROW];  // 4 sequences of x (~8.3KB)

    const int warp = blockIdx.x;      // one warp per block
    const int lane = threadIdx.x;     // 0..31
    const int g    = lane >> 3;       // element within warp (0..3)
    const int m    = lane & 7;        // lane within 8-lane group

    const int e  = warp * 4 + g;      // batch element, < 4096
    const int j0 = 2 * m;             // first owned row
    const int j1 = 2 * m + 1;         // second owned row

    // ---- Preload this warp's 4 contiguous x sequences (8KB) into smem. ----
    {
        const float4* src = reinterpret_cast<const float4*>(x + (long)warp * 4 * RNN_T);
        #pragma unroll
        for (int i = 0; i < 16; i++) {
            const int idx = i * 32 + lane;        // float4 index 0..511
            const float4 v = src[idx];
            const int f   = idx * 4;
            const int row = f >> 9;               // /512
            const int col = f & 511;
            *reinterpret_cast<float4*>(&sx[row * XROW + col]) = v;
        }
    }
    __syncwarp();

    // Packed weights for both owned rows: wp0/wp1[k] = (w[j][2k], w[j][2k+1])
    unsigned long long wp0[8], wp1[8];
    {
        const float4* wa = reinterpret_cast<const float4*>(w_hh + j0 * RNN_H);
        const float4* wb = reinterpret_cast<const float4*>(w_hh + j1 * RNN_H);
        #pragma unroll
        for (int q = 0; q < 4; q++) {
            float4 ra = wa[q], rb = wb[q];
            wp0[q * 2 + 0] = packf2(ra.x, ra.y);
            wp0[q * 2 + 1] = packf2(ra.z, ra.w);
            wp1[q * 2 + 0] = packf2(rb.x, rb.y);
            wp1[q * 2 + 1] = packf2(rb.z, rb.w);
        }
    }
    const float wih0  = w_ih[j0];
    const float wih1  = w_ih[j1];
    const float bias0 = b_ih[j0] + b_hh[j0];
    const float bias1 = b_ih[j1] + b_hh[j1];

    const float4* sx4 = reinterpret_cast<const float4*>(&sx[g * XROW]);

    // Lane state: packed (h_j0, h_j1) f32x2 — doubles as shuffle payload.
    unsigned long long hq = packf2(0.0f, 0.0f);

    #pragma unroll 1
    for (int t4 = 0; t4 < RNN_T / 4; t4++) {
        const float4 xv = sx4[t4];    // broadcast LDS.128 within each group
        const float xs[4] = {xv.x, xv.y, xv.z, xv.w};

        // Hoisted seeds for all 4 substeps (pure f(x): off the h-chain).
        unsigned long long seeds0[4], seeds1[4];
        #pragma unroll
        for (int s = 0; s < 4; s++) {
            seeds0[s] = packf2(fmaf(xs[s], wih0, bias0), 0.0f);
            seeds1[s] = packf2(fmaf(xs[s], wih1, bias1), 0.0f);
        }

        #pragma unroll
        for (int s = 0; s < 4; s++) {
            // Shuffles first — immediately consume-ordered after hq's pack.
            const unsigned long long p0 = __shfl_sync(0xffffffffu, hq, 0, 8);
            const unsigned long long p1 = __shfl_sync(0xffffffffu, hq, 1, 8);
            const unsigned long long p2 = __shfl_sync(0xffffffffu, hq, 2, 8);
            const unsigned long long p3 = __shfl_sync(0xffffffffu, hq, 3, 8);
            const unsigned long long p4 = __shfl_sync(0xffffffffu, hq, 4, 8);
            const unsigned long long p5 = __shfl_sync(0xffffffffu, hq, 5, 8);
            const unsigned long long p6 = __shfl_sync(0xffffffffu, hq, 6, 8);
            const unsigned long long p7 = __shfl_sync(0xffffffffu, hq, 7, 8);

            // Reduce p0..p6 into `partial` (completes while p7 in flight).
            unsigned long long a0 = fma2(wp0[0], p0, seeds0[s]);
            unsigned long long b0 = fma2(wp1[0], p0, seeds1[s]);
            unsigned long long a1 = mul2(wp0[1], p1);
            unsigned long long b1 = mul2(wp1[1], p1);
            unsigned long long a2 = mul2(wp0[2], p2);
            unsigned long long b2 = mul2(wp1[2], p2);
            a0 = fma2(wp0[3], p3, a0);
            b0 = fma2(wp1[3], p3, b0);
            a1 = fma2(wp0[4], p4, a1);
            b1 = fma2(wp1[4], p4, b1);
            a2 = fma2(wp0[5], p5, a2);
            b2 = fma2(wp1[5], p5, b2);
            a0 = fma2(wp0[6], p6, a0);
            b0 = fma2(wp1[6], p6, b0);
            a1 = add2(a1, a2);
            b1 = add2(b1, b2);
            const unsigned long long partA = add2(a0, a1);
            const unsigned long long partB = add2(b0, b1);

            // Late merge of the last-arriving pair, then the activation.
            const float2 prA = unpackf2(fma2(wp0[7], p7, partA));
            const float2 prB = unpackf2(fma2(wp1[7], p7, partB));

            const float h0 = tanh_approx(prA.x + prA.y);
            const float h1 = tanh_approx(prB.x + prB.y);
            hq = packf2(h0, h1);      // single pack per step
        }
    }

    // out[e] = sum_j h[j]*w_fc[j] + b_fc  (reduce over the 8-lane group)
    const float2 hf = unpackf2(hq);
    float v = hf.x * w_fc[j0] + hf.y * w_fc[j1];
    #pragma unroll
    for (int off = 4; off; off >>= 1)
        v += __shfl_xor_sync(0xffffffffu, v, off, 8);
    if (m == 0)
        out[e] = v + b_fc[0];
}

extern "C" void kernel_launch(void* const* d_in, const int* in_sizes, int n_in,
                              void* d_out, int out_size) {
    const float* x    = (const float*)d_in[0];
    const float* w_ih = (const float*)d_in[1];
    const float* w_hh = (const float*)d_in[2];
    const float* b_ih = (const float*)d_in[3];
    const float* b_hh = (const float*)d_in[4];
    const float* w_fc = (const float*)d_in[5];
    const float* b_fc = (const float*)d_in[6];
    float* out = (float*)d_out;

    // 1024 single-warp blocks; 4 batch elements per warp, 8 lanes each.
    rnn_scan_kernel<<<RNN_B / 4, 32>>>(x, w_ih, w_hh, b_ih, b_hh, w_fc, b_fc, out);
}